// round 2
// baseline (speedup 1.0000x reference)
#include <cuda_runtime.h>
#include <cuda_bf16.h>
#include <math.h>

// Problem constants
#define NB 16
#define FH 192
#define FW 192
#define NA 9
#define N_ANCH (FH*FW*NA)   // 331776
#define PRE 6000
#define POST 1000
#define CAND_CAP 8192
#define NBINS 65536
#define IOU_THR 0.7f
#define MWORDS 192          // padded words per mask row (cols up to 6144)
#define NWORDS 188          // ceil(6000/32)

// ---------------- static scratch ----------------
__device__ unsigned g_hist[NB * NBINS];
__device__ unsigned g_cnt[NB];
__device__ unsigned g_tbin[NB];
__device__ unsigned long long g_cand[NB * CAND_CAP];
__device__ float4 g_boxes[NB * PRE];
__device__ float  g_area[NB * PRE];
__device__ unsigned g_mask[(size_t)NB * PRE * MWORDS];   // 73.7 MB

// ---------------- K0: zero counters + histogram ----------------
__global__ void k_zero() {
    int i = blockIdx.x * blockDim.x + threadIdx.x;
    if (i < NB * NBINS) g_hist[i] = 0;
    if (i < NB) g_cnt[i] = 0;
}

// ---------------- K1: per-image histogram of score bits ----------------
__global__ void k_hist(const float* __restrict__ labels) {
    int n = blockIdx.x * blockDim.x + threadIdx.x;
    int img = blockIdx.y;
    unsigned key = __float_as_uint(labels[(size_t)img * N_ANCH + n]);
    unsigned bin = min(key >> 14, (unsigned)(NBINS - 1));
    atomicAdd(&g_hist[img * NBINS + bin], 1u);
}

// ---------------- K2: threshold bin so count(bin >= T) >= PRE ----------------
__global__ void k_thresh() {
    int img = blockIdx.x, tid = threadIdx.x;
    __shared__ unsigned sc[1024];
    __shared__ int found;
    __shared__ unsigned runBase;
    if (tid == 0) { found = 0; runBase = 0; }
    __syncthreads();
    for (int cs = NBINS - 1024; cs >= 0; cs -= 1024) {
        sc[tid] = g_hist[img * NBINS + cs + tid];
        __syncthreads();
        if (tid == 0) {
            unsigned run = runBase;
            for (int t = 1023; t >= 0; t--) {
                unsigned c = sc[t];
                if (run + c >= PRE) { g_tbin[img] = (unsigned)(cs + t); found = 1; break; }
                run += c;
            }
            runBase = run;
        }
        __syncthreads();
        if (found) return;
    }
    if (tid == 0) g_tbin[img] = 0;
}

// ---------------- K3: compact candidates (warp-aggregated atomics) ----------------
__global__ void k_compact(const float* __restrict__ labels) {
    int n = blockIdx.x * blockDim.x + threadIdx.x;
    int img = blockIdx.y;
    int lane = threadIdx.x & 31;
    unsigned key = __float_as_uint(labels[(size_t)img * N_ANCH + n]);
    unsigned bin = min(key >> 14, (unsigned)(NBINS - 1));
    bool pred = (bin >= g_tbin[img]);
    unsigned mask = __ballot_sync(0xFFFFFFFFu, pred);
    if (!mask) return;
    int leader = __ffs(mask) - 1;
    unsigned base = 0;
    if (lane == leader) base = atomicAdd(&g_cnt[img], (unsigned)__popc(mask));
    base = __shfl_sync(0xFFFFFFFFu, base, leader);
    if (pred) {
        unsigned pos = base + __popc(mask & ((1u << lane) - 1u));
        if (pos < CAND_CAP)
            g_cand[img * CAND_CAP + pos] =
                ((unsigned long long)(~key) << 32) | (unsigned)n;
    }
}

// ---------------- K4: per-image bitonic sort of 8192 keys ----------------
__global__ void k_sort() {
    extern __shared__ unsigned long long s[];
    int img = blockIdx.x, tid = threadIdx.x;
    unsigned M = min(g_cnt[img], (unsigned)CAND_CAP);
    for (int j = tid; j < CAND_CAP; j += 1024)
        s[j] = (j < (int)M) ? g_cand[img * CAND_CAP + j] : 0xFFFFFFFFFFFFFFFFull;
    __syncthreads();
    for (int k = 2; k <= CAND_CAP; k <<= 1) {
        for (int j = k >> 1; j > 0; j >>= 1) {
            for (int i = tid; i < CAND_CAP; i += 1024) {
                int ixj = i ^ j;
                if (ixj > i) {
                    bool up = ((i & k) == 0);
                    unsigned long long a = s[i], b = s[ixj];
                    if ((a > b) == up) { s[i] = b; s[ixj] = a; }
                }
            }
            __syncthreads();
        }
    }
    for (int j = tid; j < PRE; j += 1024)
        g_cand[img * CAND_CAP + j] = s[j];
}

// ---------------- K5: decode top-PRE boxes, clip, area ----------------
__global__ void k_decode(const float* __restrict__ deltas,
                         const float* __restrict__ base) {
    int p = blockIdx.x * blockDim.x + threadIdx.x;
    int img = blockIdx.y;
    if (p >= PRE) return;
    unsigned long long key = g_cand[img * CAND_CAP + p];
    unsigned idx = (unsigned)key;
    int a = idx % NA;
    int cell = idx / NA;
    int row = cell / FW;
    int col = cell % FW;
    float cy = ((float)row + 0.5f) / (float)FH;
    float cx = ((float)col + 0.5f) / (float)FW;
    float b0 = base[a * 4 + 0], b1 = base[a * 4 + 1];
    float b2 = base[a * 4 + 2], b3 = base[a * 4 + 3];
    float ay1 = fminf(fmaxf(cy + b0, 0.f), 1.f);
    float ax1 = fminf(fmaxf(cx + b1, 0.f), 1.f);
    float ay2 = fminf(fmaxf(cy + b2, 0.f), 1.f);
    float ax2 = fminf(fmaxf(cx + b3, 0.f), 1.f);
    float ah = ay2 - ay1, aw = ax2 - ax1;
    float acy = ay1 + 0.5f * ah, acx = ax1 + 0.5f * aw;
    const float4 d = *(const float4*)(deltas +
        ((size_t)((size_t)img * FH + row) * FW + col) * (NA * 4) + a * 4);
    float h = expf(d.z * 0.2f) * ah;
    float w = expf(d.w * 0.2f) * aw;
    float ccy = d.x * 0.1f * ah + acy;
    float ccx = d.y * 0.1f * aw + acx;
    float y1 = fminf(fmaxf(ccy - 0.5f * h, 0.f), 1.f);
    float x1 = fminf(fmaxf(ccx - 0.5f * w, 0.f), 1.f);
    float y2 = fminf(fmaxf(ccy + 0.5f * h, 0.f), 1.f);
    float x2 = fminf(fmaxf(ccx + 0.5f * w, 0.f), 1.f);
    g_boxes[img * PRE + p] = make_float4(y1, x1, y2, x2);
    g_area[img * PRE + p] = fmaxf(y2 - y1, 0.f) * fmaxf(x2 - x1, 0.f);
}

// ---------------- K6: suppression bitmask (upper triangle) ----------------
// grid (47, 48, NB), block 128. Each thread: one row i, 4 mask words (128 cols).
__global__ void k_mask() {
    __shared__ float4 sbx[128];
    __shared__ float  sar[128];
    int img = blockIdx.z;
    int i = blockIdx.x * 128 + threadIdx.x;
    int j0 = blockIdx.y * 128;

    int jj = j0 + threadIdx.x;
    if (jj < PRE) {
        sbx[threadIdx.x] = g_boxes[img * PRE + jj];
        sar[threadIdx.x] = g_area[img * PRE + jj];
    } else {
        sbx[threadIdx.x] = make_float4(0.f, 0.f, 0.f, 0.f);
        sar[threadIdx.x] = 0.f;
    }
    __syncthreads();
    if (i >= PRE) return;

    unsigned w0 = 0, w1 = 0, w2 = 0, w3 = 0;
    if (j0 + 127 > i) {   // block has columns j > i
        float4 b = g_boxes[img * PRE + i];
        float ai = g_area[img * PRE + i] + 1e-8f;
        unsigned wr[4];
        #pragma unroll
        for (int wl = 0; wl < 4; wl++) {
            unsigned bits = 0;
            #pragma unroll
            for (int t = 0; t < 32; t++) {
                int j = j0 + wl * 32 + t;
                float4 c = sbx[wl * 32 + t];
                float y1 = fmaxf(b.x, c.x), x1 = fmaxf(b.y, c.y);
                float y2 = fminf(b.z, c.z), x2 = fminf(b.w, c.w);
                float inter = fmaxf(y2 - y1, 0.f) * fmaxf(x2 - x1, 0.f);
                bool sup = (inter > IOU_THR * (ai + sar[wl * 32 + t] - inter))
                           && (j > i) && (j < PRE);
                bits |= ((unsigned)sup) << t;
            }
            wr[wl] = bits;
        }
        w0 = wr[0]; w1 = wr[1]; w2 = wr[2]; w3 = wr[3];
    }
    unsigned* dst = g_mask + ((size_t)img * PRE + i) * MWORDS + blockIdx.y * 4;
    *(uint4*)dst = make_uint4(w0, w1, w2, w3);
}

// ---------------- K7: serial mask reduce, one warp per image ----------------
__global__ void k_reduce(float* __restrict__ out) {
    __shared__ unsigned sh[MWORDS];
    __shared__ unsigned accm[MWORDS];
    int img = blockIdx.x;
    int lane = threadIdx.x;
    const unsigned* mask = g_mask + (size_t)img * PRE * MWORDS;

    for (int t = lane; t < MWORDS; t += 32) { sh[t] = 0; accm[t] = 0; }
    __syncwarp();

    int emit = 0;
    // prefetch column word 0: lane b holds row b's word 0
    unsigned colv = 0;
    if (lane < PRE) colv = mask[(size_t)lane * MWORDS + 0];

    for (int w = 0; w < NWORDS && emit < POST; w++) {
        unsigned valid = (w == NWORDS - 1) ? 0xFFFFu : 0xFFFFFFFFu;
        unsigned cur = sh[w];
        unsigned colcur = colv;
        // prefetch next column (row (w+1)*32+lane, word w+1)
        colv = 0;
        if (w + 1 < NWORDS) {
            int i2 = (w + 1) * 32 + lane;
            if (i2 < PRE) colv = mask[(size_t)i2 * MWORDS + (w + 1)];
        }
        unsigned live = ~cur & valid;
        unsigned am = 0;
        while (live && emit < POST) {
            int b = __ffs(live) - 1;
            unsigned rv = __shfl_sync(0xFFFFFFFFu, colcur, b);
            am |= (1u << b);
            emit++;
            live &= ~rv;
            live &= ~(1u << b);
        }
        if (am) {
            accm[w] = am;
            // OR accepted rows into remaining words; loads across rows are
            // independent (MLP = popc(am)) so this is ~one L2 round trip.
            for (int t = w + 1 + lane; t < MWORDS; t += 32) {
                unsigned v = 0;
                unsigned amx = am;
                while (amx) {
                    int b = __ffs(amx) - 1; amx &= amx - 1;
                    v |= mask[(size_t)(w * 32 + b) * MWORDS + t];
                }
                sh[t] |= v;
            }
        }
        __syncwarp();
    }

    // ---- emission: ascending index == selection order ----
    // lane handles contiguous word chunk [lane*6, lane*6+6)
    int lsum = 0;
    #pragma unroll
    for (int c = 0; c < 6; c++) {
        int w = lane * 6 + c;
        if (w < MWORDS) lsum += __popc(accm[w]);
    }
    unsigned x = (unsigned)lsum;
    #pragma unroll
    for (int o = 1; o < 32; o <<= 1) {
        unsigned y = __shfl_up_sync(0xFFFFFFFFu, x, o);
        if (lane >= o) x += y;
    }
    int pos = (int)x - lsum;   // exclusive prefix
    float4* out4 = (float4*)out + (size_t)img * POST;
    #pragma unroll
    for (int c = 0; c < 6; c++) {
        int w = lane * 6 + c;
        if (w >= MWORDS) break;
        unsigned m = accm[w];
        while (m) {
            int b = __ffs(m) - 1; m &= m - 1;
            int i = w * 32 + b;
            out4[pos] = g_boxes[img * PRE + i];
            pos++;
        }
    }
    // zero-pad the rest
    for (int r = emit + lane; r < POST; r += 32)
        out4[r] = make_float4(0.f, 0.f, 0.f, 0.f);
}

// ---------------- launch ----------------
extern "C" void kernel_launch(void* const* d_in, const int* in_sizes, int n_in,
                              void* d_out, int out_size) {
    const float* deltas = (const float*)d_in[0];
    const float* labels = (const float*)d_in[1];
    const float* base   = (const float*)d_in[2];
    float* out = (float*)d_out;

    cudaFuncSetAttribute(k_sort, cudaFuncAttributeMaxDynamicSharedMemorySize, CAND_CAP * 8);

    k_zero<<<(NB * NBINS + 255) / 256, 256>>>();
    dim3 gfull(N_ANCH / 256, NB);
    k_hist<<<gfull, 256>>>(labels);
    k_thresh<<<NB, 1024>>>();
    k_compact<<<gfull, 256>>>(labels);
    k_sort<<<NB, 1024, CAND_CAP * 8>>>();
    dim3 gdec((PRE + 255) / 256, NB);
    k_decode<<<gdec, 256>>>(deltas, base);
    dim3 gmask((PRE + 127) / 128, MWORDS / 4, NB);
    k_mask<<<gmask, 128>>>();
    k_reduce<<<NB, 32>>>(out);
}

// round 3
// speedup vs baseline: 1.7829x; 1.7829x over previous
#include <cuda_runtime.h>
#include <cuda_bf16.h>
#include <math.h>

// Problem constants
#define NB 16
#define FH 192
#define FW 192
#define NA 9
#define N_ANCH (FH*FW*NA)   // 331776
#define PRE 6000
#define POST 1000
#define CAND_CAP 8192
#define NBINS 65536
#define IOU_THR 0.7f
#define NTILES ((PRE + 31) / 32)   // 188

// ---------------- static scratch ----------------
__device__ unsigned g_hist[NB * NBINS];
__device__ unsigned g_cnt[NB];
__device__ unsigned g_tbin[NB];
__device__ unsigned long long g_cand[NB * CAND_CAP];
__device__ float4 g_boxes[NB * PRE];
__device__ float  g_area[NB * PRE];

// ---------------- K0: zero counters + histogram ----------------
__global__ void k_zero() {
    int i = blockIdx.x * blockDim.x + threadIdx.x;
    if (i < NB * NBINS / 4) ((uint4*)g_hist)[i] = make_uint4(0, 0, 0, 0);
    if (i < NB) g_cnt[i] = 0;
}

// ---------------- K1: per-image histogram (float4 loads, MLP=4) ----------------
// grid (N_ANCH/4/256, NB) x 256
__global__ void k_hist(const float* __restrict__ labels) {
    int i = blockIdx.x * blockDim.x + threadIdx.x;
    int img = blockIdx.y;
    float4 v = ((const float4*)(labels + (size_t)img * N_ANCH))[i];
    unsigned* h = g_hist + img * NBINS;
    atomicAdd(&h[min(__float_as_uint(v.x) >> 14, (unsigned)(NBINS - 1))], 1u);
    atomicAdd(&h[min(__float_as_uint(v.y) >> 14, (unsigned)(NBINS - 1))], 1u);
    atomicAdd(&h[min(__float_as_uint(v.z) >> 14, (unsigned)(NBINS - 1))], 1u);
    atomicAdd(&h[min(__float_as_uint(v.w) >> 14, (unsigned)(NBINS - 1))], 1u);
}

// ---------------- K2: threshold bin so count(bin >= T) >= PRE ----------------
__global__ void k_thresh() {
    int img = blockIdx.x, tid = threadIdx.x;
    __shared__ unsigned sc[1024];
    __shared__ int found;
    __shared__ unsigned runBase;
    if (tid == 0) { found = 0; runBase = 0; }
    __syncthreads();
    for (int cs = NBINS - 1024; cs >= 0; cs -= 1024) {
        sc[tid] = g_hist[img * NBINS + cs + tid];
        __syncthreads();
        if (tid == 0) {
            unsigned run = runBase;
            for (int t = 1023; t >= 0; t--) {
                unsigned c = sc[t];
                if (run + c >= PRE) { g_tbin[img] = (unsigned)(cs + t); found = 1; break; }
                run += c;
            }
            runBase = run;
        }
        __syncthreads();
        if (found) return;
    }
    if (tid == 0) g_tbin[img] = 0;
}

// ---------------- K3: compact candidates (float4 loads) ----------------
__global__ void k_compact(const float* __restrict__ labels) {
    int i = blockIdx.x * blockDim.x + threadIdx.x;
    int img = blockIdx.y;
    float4 v = ((const float4*)(labels + (size_t)img * N_ANCH))[i];
    unsigned tb = g_tbin[img];
    float key[4] = {v.x, v.y, v.z, v.w};
    #pragma unroll
    for (int c = 0; c < 4; c++) {
        unsigned k = __float_as_uint(key[c]);
        unsigned bin = min(k >> 14, (unsigned)(NBINS - 1));
        if (bin >= tb) {
            unsigned pos = atomicAdd(&g_cnt[img], 1u);
            if (pos < CAND_CAP)
                g_cand[img * CAND_CAP + pos] =
                    ((unsigned long long)(~k) << 32) | (unsigned)(i * 4 + c);
        }
    }
}

// ---------------- K4: per-image bitonic sort of 8192 keys ----------------
__global__ void k_sort() {
    extern __shared__ unsigned long long s[];
    int img = blockIdx.x, tid = threadIdx.x;
    unsigned M = min(g_cnt[img], (unsigned)CAND_CAP);
    for (int j = tid; j < CAND_CAP; j += 1024)
        s[j] = (j < (int)M) ? g_cand[img * CAND_CAP + j] : 0xFFFFFFFFFFFFFFFFull;
    __syncthreads();
    for (int k = 2; k <= CAND_CAP; k <<= 1) {
        for (int j = k >> 1; j > 0; j >>= 1) {
            for (int i = tid; i < CAND_CAP; i += 1024) {
                int ixj = i ^ j;
                if (ixj > i) {
                    bool up = ((i & k) == 0);
                    unsigned long long a = s[i], b = s[ixj];
                    if ((a > b) == up) { s[i] = b; s[ixj] = a; }
                }
            }
            __syncthreads();
        }
    }
    for (int j = tid; j < PRE; j += 1024)
        g_cand[img * CAND_CAP + j] = s[j];
}

// ---------------- K5: decode top-PRE boxes, clip, area ----------------
__global__ void k_decode(const float* __restrict__ deltas,
                         const float* __restrict__ base) {
    int p = blockIdx.x * blockDim.x + threadIdx.x;
    int img = blockIdx.y;
    if (p >= PRE) return;
    unsigned long long key = g_cand[img * CAND_CAP + p];
    unsigned idx = (unsigned)key;
    int a = idx % NA;
    int cell = idx / NA;
    int row = cell / FW;
    int col = cell % FW;
    float cy = ((float)row + 0.5f) / (float)FH;
    float cx = ((float)col + 0.5f) / (float)FW;
    float b0 = base[a * 4 + 0], b1 = base[a * 4 + 1];
    float b2 = base[a * 4 + 2], b3 = base[a * 4 + 3];
    float ay1 = fminf(fmaxf(cy + b0, 0.f), 1.f);
    float ax1 = fminf(fmaxf(cx + b1, 0.f), 1.f);
    float ay2 = fminf(fmaxf(cy + b2, 0.f), 1.f);
    float ax2 = fminf(fmaxf(cx + b3, 0.f), 1.f);
    float ah = ay2 - ay1, aw = ax2 - ax1;
    float acy = ay1 + 0.5f * ah, acx = ax1 + 0.5f * aw;
    const float4 d = *(const float4*)(deltas +
        ((size_t)((size_t)img * FH + row) * FW + col) * (NA * 4) + a * 4);
    float h = expf(d.z * 0.2f) * ah;
    float w = expf(d.w * 0.2f) * aw;
    float ccy = d.x * 0.1f * ah + acy;
    float ccx = d.y * 0.1f * aw + acx;
    float y1 = fminf(fmaxf(ccy - 0.5f * h, 0.f), 1.f);
    float x1 = fminf(fmaxf(ccx - 0.5f * w, 0.f), 1.f);
    float y2 = fminf(fmaxf(ccy + 0.5f * h, 0.f), 1.f);
    float x2 = fminf(fmaxf(ccx + 0.5f * w, 0.f), 1.f);
    g_boxes[img * PRE + p] = make_float4(y1, x1, y2, x2);
    g_area[img * PRE + p] = fmaxf(y2 - y1, 0.f) * fmaxf(x2 - x1, 0.f);
}

// ---------------- K6: tiled greedy NMS, one block per image ----------------
// Tiles of 32 candidates in sorted order. Warp 0 resolves acceptance inside
// the tile (register/ballot bit logic, cost ~ live lanes); then all threads
// sweep later candidates against the tile's accepted boxes (<=32).
#define NMS_THREADS 512
#define SM_BOXES 0
#define SM_AREA  96000
#define SM_LIVE  120000
#define SM_TOTAL 126016   // 96000 + 24000 + 6016

__global__ void k_nms(float* __restrict__ out) {
    extern __shared__ char sm[];
    float4* sb = (float4*)(sm + SM_BOXES);
    float* sa = (float*)(sm + SM_AREA);
    unsigned char* live = (unsigned char*)(sm + SM_LIVE);
    __shared__ float4 accb[32];
    __shared__ float acca[32];
    __shared__ int s_nacc, s_emit, s_stop;

    int img = blockIdx.x, tid = threadIdx.x;
    for (int j = tid; j < PRE; j += NMS_THREADS) {
        sb[j] = g_boxes[img * PRE + j];
        sa[j] = g_area[img * PRE + j];
        live[j] = 1;
    }
    if (tid == 0) { s_emit = 0; s_stop = 0; }
    __syncthreads();

    float4* out4 = (float4*)out + (size_t)img * POST;

    for (int tile = 0; tile < NTILES; tile++) {
        int tbase = tile * 32;
        // ---- warp 0: resolve tile ----
        if (tid < 32) {
            int j = tbase + tid;
            bool lv = (j < PRE) && live[j];
            unsigned liveM = __ballot_sync(0xFFFFFFFFu, lv);
            int na = 0;
            if (liveM) {
                float4 b = lv ? sb[j] : make_float4(0.f, 0.f, 0.f, 0.f);
                float aj = lv ? sa[j] : 0.f;
                // suppressor mask: live lanes k < me with IoU > thr
                unsigned sup = 0;
                unsigned mIter = liveM;
                while (mIter) {
                    int k = __ffs(mIter) - 1; mIter &= mIter - 1;
                    float4 bk = sb[tbase + k];   // broadcast LDS
                    float ak = sa[tbase + k];
                    float y1 = fmaxf(b.x, bk.x), x1 = fmaxf(b.y, bk.y);
                    float y2 = fminf(b.z, bk.z), x2 = fminf(b.w, bk.w);
                    float inter = fmaxf(y2 - y1, 0.f) * fmaxf(x2 - x1, 0.f);
                    bool s = (k < tid) && lv &&
                             (inter > IOU_THR * (ak + 1e-8f + aj - inter));
                    sup |= ((unsigned)s) << k;
                }
                // serial resolution via ballots (all lanes in lockstep)
                int emit0 = s_emit;
                int room = POST - emit0;
                unsigned acc = 0;
                unsigned rem = liveM;
                while (rem && na < room) {
                    int j2 = __ffs(rem) - 1;
                    acc |= 1u << j2;
                    na++;
                    unsigned dead = __ballot_sync(0xFFFFFFFFu, (sup >> j2) & 1u);
                    rem &= ~dead;
                    rem &= ~(1u << j2);
                }
                if ((acc >> tid) & 1u) {
                    int ord = __popc(acc & ((1u << tid) - 1u));
                    out4[emit0 + ord] = b;
                    accb[ord] = b;
                    acca[ord] = aj;
                }
                if (tid == 0) {
                    s_emit = emit0 + na;
                    if (s_emit >= POST) s_stop = 1;
                }
            }
            if (tid == 0) s_nacc = na;
        }
        __syncthreads();
        int na = s_nacc;
        if (s_stop) break;
        // ---- sweep: kill later candidates vs accepted boxes of this tile ----
        if (na) {
            for (int j = tbase + 32 + tid; j < PRE; j += NMS_THREADS) {
                if (!live[j]) continue;
                float4 c = sb[j];
                float acj = sa[j];
                bool kill = false;
                for (int q = 0; q < na; q++) {
                    float4 b = accb[q];
                    float y1 = fmaxf(b.x, c.x), x1 = fmaxf(b.y, c.y);
                    float y2 = fminf(b.z, c.z), x2 = fminf(b.w, c.w);
                    float inter = fmaxf(y2 - y1, 0.f) * fmaxf(x2 - x1, 0.f);
                    if (inter > IOU_THR * (acca[q] + 1e-8f + acj - inter)) {
                        kill = true; break;
                    }
                }
                if (kill) live[j] = 0;
            }
        }
        __syncthreads();
    }
    // zero-pad remaining rows
    for (int r = s_emit + tid; r < POST; r += NMS_THREADS)
        out4[r] = make_float4(0.f, 0.f, 0.f, 0.f);
}

// ---------------- launch ----------------
extern "C" void kernel_launch(void* const* d_in, const int* in_sizes, int n_in,
                              void* d_out, int out_size) {
    const float* deltas = (const float*)d_in[0];
    const float* labels = (const float*)d_in[1];
    const float* base   = (const float*)d_in[2];
    float* out = (float*)d_out;

    cudaFuncSetAttribute(k_sort, cudaFuncAttributeMaxDynamicSharedMemorySize, CAND_CAP * 8);
    cudaFuncSetAttribute(k_nms, cudaFuncAttributeMaxDynamicSharedMemorySize, SM_TOTAL);

    k_zero<<<(NB * NBINS / 4 + 255) / 256, 256>>>();
    dim3 gq(N_ANCH / 4 / 256, NB);
    k_hist<<<gq, 256>>>(labels);
    k_thresh<<<NB, 1024>>>();
    k_compact<<<gq, 256>>>(labels);
    k_sort<<<NB, 1024, CAND_CAP * 8>>>();
    dim3 gdec((PRE + 255) / 256, NB);
    k_decode<<<gdec, 256>>>(deltas, base);
    k_nms<<<NB, NMS_THREADS, SM_TOTAL>>>(out);
}

// round 4
// speedup vs baseline: 2.2249x; 1.2479x over previous
#include <cuda_runtime.h>
#include <cuda_bf16.h>
#include <math.h>

// Problem constants
#define NB 16
#define FH 192
#define FW 192
#define NA 9
#define N_ANCH (FH*FW*NA)   // 331776
#define PRE 6000
#define POST 1000
#define CAND_CAP 8192
#define IOU_THR 0.7f
#define NTILES ((PRE + 31) / 32)   // 188
#define NBIN2 2050                 // 0: <0.5 | 1..2048: [0.5,1) by mantissa[22:12] | 2049: >=1.0
#define SEG_MAX 512

// ---------------- static scratch ----------------
__device__ unsigned g_hist2[NB * NBIN2];
__device__ unsigned g_bcnt[NB * NBIN2];
__device__ unsigned g_segstart[NB * NBIN2];
__device__ unsigned g_tbin2[NB];
__device__ unsigned g_ticket;
__device__ unsigned long long g_cand[NB * CAND_CAP];
__device__ float4 g_boxes[NB * PRE];
__device__ float  g_area[NB * PRE];

__device__ __forceinline__ int score_bin(unsigned k) {
    if (k >= 0x3F800000u) return NBIN2 - 1;
    if (k >= 0x3F000000u) return 1 + (int)((k >> 12) & 0x7FFu);
    return 0;
}

// ---------------- K0: zero counters ----------------
__global__ void k_zero() {
    int i = blockIdx.x * blockDim.x + threadIdx.x;
    if (i < NB * NBIN2) { g_hist2[i] = 0; g_bcnt[i] = 0; }
    if (i == 0) g_ticket = 0;
}

// ---------------- K1: shared-mem histogram + fused threshold (last block) ----------------
// grid (18, NB) x 256 : per block 18432 elements = 4608 float4 = 18/thread
#define HB 18
__global__ void k_histthresh(const float* __restrict__ labels) {
    __shared__ unsigned sh[NBIN2];
    int img = blockIdx.y, tid = threadIdx.x;
    for (int t = tid; t < NBIN2; t += 256) sh[t] = 0;
    __syncthreads();
    const float4* L = (const float4*)(labels + (size_t)img * N_ANCH);
    int base = blockIdx.x * 4608;
    #pragma unroll
    for (int p = 0; p < 18; p++) {
        float4 v = L[base + p * 256 + tid];
        atomicAdd(&sh[score_bin(__float_as_uint(v.x))], 1u);
        atomicAdd(&sh[score_bin(__float_as_uint(v.y))], 1u);
        atomicAdd(&sh[score_bin(__float_as_uint(v.z))], 1u);
        atomicAdd(&sh[score_bin(__float_as_uint(v.w))], 1u);
    }
    __syncthreads();
    for (int t = tid; t < NBIN2; t += 256) {
        unsigned c = sh[t];
        if (c) atomicAdd(&g_hist2[img * NBIN2 + t], c);
    }
    // ---- last-block does the threshold + segment offsets for all images ----
    __threadfence();
    __shared__ int isLast;
    __syncthreads();
    if (tid == 0) isLast = (atomicAdd(&g_ticket, 1u) == (unsigned)(gridDim.x * gridDim.y - 1));
    __syncthreads();
    if (!isLast) return;

    int w = tid >> 5, lane = tid & 31;       // warp w handles image w (need >=16 warps? 256thr=8 warps)
    for (int im = w; im < NB; im += 8) {
        const unsigned* h = g_hist2 + im * NBIN2;
        unsigned* ss = g_segstart + im * NBIN2;
        unsigned run = 0;
        int T = -1;
        for (int c = 0; c < (NBIN2 + 31) / 32 && T < 0; c++) {
            int b = (NBIN2 - 1) - (c * 32 + lane);     // descending bins
            unsigned cnt = (b >= 0) ? h[b] : 0u;
            unsigned inc = cnt;
            #pragma unroll
            for (int o = 1; o < 32; o <<= 1) {
                unsigned v = __shfl_up_sync(0xFFFFFFFFu, inc, o);
                if (lane >= o) inc += v;
            }
            if (b >= 0) ss[b] = run + inc - cnt;
            unsigned tot = __shfl_sync(0xFFFFFFFFu, inc, 31);
            unsigned hit = __ballot_sync(0xFFFFFFFFu, b >= 0 && (run + inc) >= PRE);
            if (hit) T = (NBIN2 - 1) - (c * 32 + (__ffs(hit) - 1));
            run += tot;
        }
        if (lane == 0) g_tbin2[im] = (T < 0) ? 0u : (unsigned)T;
    }
}

// ---------------- K2: compact + exact bin placement ----------------
// grid (81, NB) x 256 : 81*256*16 = 331776 floats per image
__global__ void k_compact(const float* __restrict__ labels) {
    int img = blockIdx.y, tid = threadIdx.x;
    const float4* L = (const float4*)(labels + (size_t)img * N_ANCH);
    int tb = (int)g_tbin2[img];
    const unsigned* ss = g_segstart + img * NBIN2;
    unsigned* bc = g_bcnt + img * NBIN2;
    int base = blockIdx.x * 1024;            // in float4 units
    #pragma unroll
    for (int p = 0; p < 4; p++) {
        int f4 = base + p * 256 + tid;
        float4 v = L[f4];
        float e[4] = {v.x, v.y, v.z, v.w};
        #pragma unroll
        for (int c = 0; c < 4; c++) {
            unsigned k = __float_as_uint(e[c]);
            int b = score_bin(k);
            if (b >= tb) {
                unsigned pos = ss[b] + atomicAdd(&bc[b], 1u);
                if (pos < CAND_CAP)
                    g_cand[img * CAND_CAP + pos] =
                        ((unsigned long long)(~k) << 32) | (unsigned)(f4 * 4 + c);
            }
        }
    }
}

// ---------------- K3: per-bin segment sort (one warp per bin) ----------------
// grid: NB * NBIN2 / 8 warps-per-block
__global__ void k_segsort() {
    __shared__ unsigned long long s[8][SEG_MAX];
    int gw = blockIdx.x * 8 + (threadIdx.x >> 5);
    int lane = threadIdx.x & 31;
    int img = gw / NBIN2;
    int b = gw % NBIN2;
    if (img >= NB) return;
    if (b < (int)g_tbin2[img]) return;
    int L = (int)g_bcnt[img * NBIN2 + b];
    if (L <= 1) return;
    if (L > SEG_MAX) L = SEG_MAX;            // never in practice
    unsigned start = g_segstart[img * NBIN2 + b];
    unsigned long long* seg = g_cand + img * CAND_CAP + start;
    unsigned long long (&sw)[SEG_MAX] = s[threadIdx.x >> 5];

    int P2 = 32; while (P2 < L) P2 <<= 1;
    for (int t = lane; t < P2; t += 32)
        sw[t] = (t < L && start + t < CAND_CAP) ? seg[t] : 0xFFFFFFFFFFFFFFFFull;
    __syncwarp();
    for (int k = 2; k <= P2; k <<= 1) {
        for (int j = k >> 1; j > 0; j >>= 1) {
            for (int i = lane; i < P2; i += 32) {
                int ixj = i ^ j;
                if (ixj > i) {
                    bool up = ((i & k) == 0);
                    unsigned long long a = sw[i], bb = sw[ixj];
                    if ((a > bb) == up) { sw[i] = bb; sw[ixj] = a; }
                }
            }
            __syncwarp();
        }
    }
    for (int t = lane; t < L; t += 32)
        if (start + t < CAND_CAP) seg[t] = sw[t];
}

// ---------------- K4: decode top-PRE boxes, clip, area ----------------
__global__ void k_decode(const float* __restrict__ deltas,
                         const float* __restrict__ base) {
    int p = blockIdx.x * blockDim.x + threadIdx.x;
    int img = blockIdx.y;
    if (p >= PRE) return;
    unsigned long long key = g_cand[img * CAND_CAP + p];
    unsigned idx = (unsigned)key;
    int a = idx % NA;
    int cell = idx / NA;
    int row = cell / FW;
    int col = cell % FW;
    float cy = ((float)row + 0.5f) / (float)FH;
    float cx = ((float)col + 0.5f) / (float)FW;
    float b0 = base[a * 4 + 0], b1 = base[a * 4 + 1];
    float b2 = base[a * 4 + 2], b3 = base[a * 4 + 3];
    float ay1 = fminf(fmaxf(cy + b0, 0.f), 1.f);
    float ax1 = fminf(fmaxf(cx + b1, 0.f), 1.f);
    float ay2 = fminf(fmaxf(cy + b2, 0.f), 1.f);
    float ax2 = fminf(fmaxf(cx + b3, 0.f), 1.f);
    float ah = ay2 - ay1, aw = ax2 - ax1;
    float acy = ay1 + 0.5f * ah, acx = ax1 + 0.5f * aw;
    const float4 d = *(const float4*)(deltas +
        ((size_t)((size_t)img * FH + row) * FW + col) * (NA * 4) + a * 4);
    float h = expf(d.z * 0.2f) * ah;
    float w = expf(d.w * 0.2f) * aw;
    float ccy = d.x * 0.1f * ah + acy;
    float ccx = d.y * 0.1f * aw + acx;
    float y1 = fminf(fmaxf(ccy - 0.5f * h, 0.f), 1.f);
    float x1 = fminf(fmaxf(ccx - 0.5f * w, 0.f), 1.f);
    float y2 = fminf(fmaxf(ccy + 0.5f * h, 0.f), 1.f);
    float x2 = fminf(fmaxf(ccx + 0.5f * w, 0.f), 1.f);
    g_boxes[img * PRE + p] = make_float4(y1, x1, y2, x2);
    g_area[img * PRE + p] = fmaxf(y2 - y1, 0.f) * fmaxf(x2 - x1, 0.f);
}

// ---------------- K5: tiled greedy NMS, one block per image ----------------
#define NMS_THREADS 512
#define SM_BOXES 0
#define SM_AREA  96000
#define SM_LIVE  120000
#define SM_TOTAL 126016

__global__ void k_nms(float* __restrict__ out) {
    extern __shared__ char sm[];
    float4* sb = (float4*)(sm + SM_BOXES);
    float* sa = (float*)(sm + SM_AREA);
    unsigned char* live = (unsigned char*)(sm + SM_LIVE);
    __shared__ float4 accb[32];
    __shared__ float acca[32];
    __shared__ int s_nacc, s_emit, s_stop;

    int img = blockIdx.x, tid = threadIdx.x;
    for (int j = tid; j < PRE; j += NMS_THREADS) {
        sb[j] = g_boxes[img * PRE + j];
        sa[j] = g_area[img * PRE + j];
        live[j] = 1;
    }
    if (tid == 0) { s_emit = 0; s_stop = 0; }
    __syncthreads();

    float4* out4 = (float4*)out + (size_t)img * POST;

    for (int tile = 0; tile < NTILES; tile++) {
        int tbase = tile * 32;
        if (tid < 32) {
            int j = tbase + tid;
            bool lv = (j < PRE) && live[j];
            unsigned liveM = __ballot_sync(0xFFFFFFFFu, lv);
            int na = 0;
            if (liveM) {
                float4 b = lv ? sb[j] : make_float4(0.f, 0.f, 0.f, 0.f);
                float aj = lv ? sa[j] : 0.f;
                unsigned sup = 0;
                unsigned mIter = liveM;
                while (mIter) {
                    int k = __ffs(mIter) - 1; mIter &= mIter - 1;
                    float4 bk = sb[tbase + k];
                    float ak = sa[tbase + k];
                    float y1 = fmaxf(b.x, bk.x), x1 = fmaxf(b.y, bk.y);
                    float y2 = fminf(b.z, bk.z), x2 = fminf(b.w, bk.w);
                    float inter = fmaxf(y2 - y1, 0.f) * fmaxf(x2 - x1, 0.f);
                    bool s = (k < tid) && lv &&
                             (inter > IOU_THR * (ak + 1e-8f + aj - inter));
                    sup |= ((unsigned)s) << k;
                }
                int emit0 = s_emit;
                int room = POST - emit0;
                unsigned acc = 0;
                unsigned rem = liveM;
                while (rem && na < room) {
                    int j2 = __ffs(rem) - 1;
                    acc |= 1u << j2;
                    na++;
                    unsigned dead = __ballot_sync(0xFFFFFFFFu, (sup >> j2) & 1u);
                    rem &= ~dead;
                    rem &= ~(1u << j2);
                }
                if ((acc >> tid) & 1u) {
                    int ord = __popc(acc & ((1u << tid) - 1u));
                    out4[emit0 + ord] = b;
                    accb[ord] = b;
                    acca[ord] = aj;
                }
                if (tid == 0) {
                    s_emit = emit0 + na;
                    if (s_emit >= POST) s_stop = 1;
                }
            }
            if (tid == 0) s_nacc = na;
        }
        __syncthreads();
        int na = s_nacc;
        if (s_stop) break;
        if (na) {
            for (int j = tbase + 32 + tid; j < PRE; j += NMS_THREADS) {
                if (!live[j]) continue;
                float4 c = sb[j];
                float acj = sa[j];
                bool kill = false;
                for (int q = 0; q < na; q++) {
                    float4 b = accb[q];
                    float y1 = fmaxf(b.x, c.x), x1 = fmaxf(b.y, c.y);
                    float y2 = fminf(b.z, c.z), x2 = fminf(b.w, c.w);
                    float inter = fmaxf(y2 - y1, 0.f) * fmaxf(x2 - x1, 0.f);
                    if (inter > IOU_THR * (acca[q] + 1e-8f + acj - inter)) {
                        kill = true; break;
                    }
                }
                if (kill) live[j] = 0;
            }
        }
        __syncthreads();
    }
    for (int r = s_emit + tid; r < POST; r += NMS_THREADS)
        out4[r] = make_float4(0.f, 0.f, 0.f, 0.f);
}

// ---------------- launch ----------------
extern "C" void kernel_launch(void* const* d_in, const int* in_sizes, int n_in,
                              void* d_out, int out_size) {
    const float* deltas = (const float*)d_in[0];
    const float* labels = (const float*)d_in[1];
    const float* base   = (const float*)d_in[2];
    float* out = (float*)d_out;

    cudaFuncSetAttribute(k_nms, cudaFuncAttributeMaxDynamicSharedMemorySize, SM_TOTAL);

    k_zero<<<(NB * NBIN2 + 255) / 256, 256>>>();                 // 1
    dim3 gh(HB, NB);
    k_histthresh<<<gh, 256>>>(labels);                           // 2
    dim3 gc(81, NB);
    k_compact<<<gc, 256>>>(labels);                              // 3
    k_segsort<<<(NB * NBIN2 + 7) / 8, 256>>>();                  // 4  <- ncu slot
    dim3 gdec((PRE + 255) / 256, NB);
    k_decode<<<gdec, 256>>>(deltas, base);                       // 5
    k_nms<<<NB, NMS_THREADS, SM_TOTAL>>>(out);                   // 6
}

// round 6
// speedup vs baseline: 3.0686x; 1.3792x over previous
#include <cuda_runtime.h>
#include <cuda_bf16.h>
#include <math.h>

// Problem constants
#define NB 16
#define FH 192
#define FW 192
#define NA 9
#define N_ANCH (FH*FW*NA)   // 331776
#define PRE 6000
#define POST 1000
#define CAND_CAP 8192
#define IOU_THR 0.7f
#define NTILES ((PRE + 31) / 32)   // 188
#define NBIN2 2050                 // 0: <0.5 | 1..2048: [0.5,1) | 2049: >=1.0
#define SEG_MAX 512

// ---------------- static scratch ----------------
__device__ unsigned g_hist2[NB * NBIN2];
__device__ unsigned g_bcnt[NB * NBIN2];
__device__ unsigned g_segstart[NB * NBIN2];
__device__ unsigned g_tbin2[NB];
__device__ unsigned g_ticket;
__device__ unsigned long long g_cand[NB * CAND_CAP];
__device__ float4 g_boxes[NB * PRE];
__device__ float  g_area[NB * PRE];

__device__ __forceinline__ int score_bin(unsigned k) {
    if (k >= 0x3F800000u) return NBIN2 - 1;
    if (k >= 0x3F000000u) return 1 + (int)((k >> 12) & 0x7FFu);
    return 0;
}

// ---------------- K0: zero counters ----------------
__global__ void k_zero() {
    int i = blockIdx.x * blockDim.x + threadIdx.x;
    if (i < NB * NBIN2) { g_hist2[i] = 0; g_bcnt[i] = 0; }
    if (i == 0) g_ticket = 0;
}

// ---------------- K1: histogram (bin0 via registers) + fused threshold ----------------
#define HB 18
__global__ void k_histthresh(const float* __restrict__ labels) {
    __shared__ unsigned sh[NBIN2];
    int img = blockIdx.y, tid = threadIdx.x;
    for (int t = tid; t < NBIN2; t += 256) sh[t] = 0;
    __syncthreads();
    const float4* L = (const float4*)(labels + (size_t)img * N_ANCH);
    int base = blockIdx.x * 4608;
    unsigned c0 = 0;
    #pragma unroll
    for (int p = 0; p < 18; p++) {
        float4 v = L[base + p * 256 + tid];
        int b0 = score_bin(__float_as_uint(v.x));
        int b1 = score_bin(__float_as_uint(v.y));
        int b2 = score_bin(__float_as_uint(v.z));
        int b3 = score_bin(__float_as_uint(v.w));
        if (b0) atomicAdd(&sh[b0], 1u); else c0++;
        if (b1) atomicAdd(&sh[b1], 1u); else c0++;
        if (b2) atomicAdd(&sh[b2], 1u); else c0++;
        if (b3) atomicAdd(&sh[b3], 1u); else c0++;
    }
    #pragma unroll
    for (int o = 16; o > 0; o >>= 1) c0 += __shfl_down_sync(0xFFFFFFFFu, c0, o);
    if ((tid & 31) == 0 && c0) atomicAdd(&sh[0], c0);
    __syncthreads();
    for (int t = tid; t < NBIN2; t += 256) {
        unsigned c = sh[t];
        if (c) atomicAdd(&g_hist2[img * NBIN2 + t], c);
    }
    // ---- last block: threshold + segment offsets for all images ----
    __threadfence();
    __shared__ int isLast;
    __syncthreads();
    if (tid == 0) isLast = (atomicAdd(&g_ticket, 1u) == (unsigned)(gridDim.x * gridDim.y - 1));
    __syncthreads();
    if (!isLast) return;

    int w = tid >> 5, lane = tid & 31;
    for (int im = w; im < NB; im += 8) {
        const unsigned* h = g_hist2 + im * NBIN2;
        unsigned* ss = g_segstart + im * NBIN2;
        unsigned run = 0;
        int T = -1;
        for (int c = 0; c < (NBIN2 + 31) / 32 && T < 0; c++) {
            int b = (NBIN2 - 1) - (c * 32 + lane);
            unsigned cnt = (b >= 0) ? h[b] : 0u;
            unsigned inc = cnt;
            #pragma unroll
            for (int o = 1; o < 32; o <<= 1) {
                unsigned v = __shfl_up_sync(0xFFFFFFFFu, inc, o);
                if (lane >= o) inc += v;
            }
            if (b >= 0) ss[b] = run + inc - cnt;
            unsigned tot = __shfl_sync(0xFFFFFFFFu, inc, 31);
            unsigned hit = __ballot_sync(0xFFFFFFFFu, b >= 0 && (run + inc) >= PRE);
            if (hit) T = (NBIN2 - 1) - (c * 32 + (__ffs(hit) - 1));
            run += tot;
        }
        if (lane == 0) g_tbin2[im] = (T < 0) ? 0u : (unsigned)T;
    }
}

// ---------------- K2: compact + exact bin placement ----------------
__global__ void k_compact(const float* __restrict__ labels) {
    int img = blockIdx.y, tid = threadIdx.x;
    const float4* L = (const float4*)(labels + (size_t)img * N_ANCH);
    int tb = (int)g_tbin2[img];
    const unsigned* ss = g_segstart + img * NBIN2;
    unsigned* bc = g_bcnt + img * NBIN2;
    int base = blockIdx.x * 1024;
    #pragma unroll
    for (int p = 0; p < 4; p++) {
        int f4 = base + p * 256 + tid;
        float4 v = L[f4];
        float e[4] = {v.x, v.y, v.z, v.w};
        #pragma unroll
        for (int c = 0; c < 4; c++) {
            unsigned k = __float_as_uint(e[c]);
            int b = score_bin(k);
            if (b >= tb) {
                unsigned pos = ss[b] + atomicAdd(&bc[b], 1u);
                if (pos < CAND_CAP)
                    g_cand[img * CAND_CAP + pos] =
                        ((unsigned long long)(~k) << 32) | (unsigned)(f4 * 4 + c);
            }
        }
    }
}

// ---------------- K3: per-bin segment sort (one warp per bin) ----------------
__global__ void k_segsort() {
    __shared__ unsigned long long s[8][SEG_MAX];
    int gw = blockIdx.x * 8 + (threadIdx.x >> 5);
    int lane = threadIdx.x & 31;
    int img = gw / NBIN2;
    int b = gw % NBIN2;
    if (img >= NB) return;
    if (b < (int)g_tbin2[img]) return;
    int L = (int)g_bcnt[img * NBIN2 + b];
    if (L <= 1) return;
    if (L > SEG_MAX) L = SEG_MAX;
    unsigned start = g_segstart[img * NBIN2 + b];
    unsigned long long* seg = g_cand + img * CAND_CAP + start;
    unsigned long long (&sw)[SEG_MAX] = s[threadIdx.x >> 5];

    int P2 = 32; while (P2 < L) P2 <<= 1;
    for (int t = lane; t < P2; t += 32)
        sw[t] = (t < L && start + t < CAND_CAP) ? seg[t] : 0xFFFFFFFFFFFFFFFFull;
    __syncwarp();
    for (int k = 2; k <= P2; k <<= 1) {
        for (int j = k >> 1; j > 0; j >>= 1) {
            for (int i = lane; i < P2; i += 32) {
                int ixj = i ^ j;
                if (ixj > i) {
                    bool up = ((i & k) == 0);
                    unsigned long long a = sw[i], bb = sw[ixj];
                    if ((a > bb) == up) { sw[i] = bb; sw[ixj] = a; }
                }
            }
            __syncwarp();
        }
    }
    for (int t = lane; t < L; t += 32)
        if (start + t < CAND_CAP) seg[t] = sw[t];
}

// ---------------- K4: decode top-PRE boxes, clip, area ----------------
__global__ void k_decode(const float* __restrict__ deltas,
                         const float* __restrict__ base) {
    int p = blockIdx.x * blockDim.x + threadIdx.x;
    int img = blockIdx.y;
    if (p >= PRE) return;
    unsigned long long key = g_cand[img * CAND_CAP + p];
    unsigned idx = (unsigned)key;
    int a = idx % NA;
    int cell = idx / NA;
    int row = cell / FW;
    int col = cell % FW;
    float cy = ((float)row + 0.5f) / (float)FH;
    float cx = ((float)col + 0.5f) / (float)FW;
    float b0 = base[a * 4 + 0], b1 = base[a * 4 + 1];
    float b2 = base[a * 4 + 2], b3 = base[a * 4 + 3];
    float ay1 = fminf(fmaxf(cy + b0, 0.f), 1.f);
    float ax1 = fminf(fmaxf(cx + b1, 0.f), 1.f);
    float ay2 = fminf(fmaxf(cy + b2, 0.f), 1.f);
    float ax2 = fminf(fmaxf(cx + b3, 0.f), 1.f);
    float ah = ay2 - ay1, aw = ax2 - ax1;
    float acy = ay1 + 0.5f * ah, acx = ax1 + 0.5f * aw;
    const float4 d = *(const float4*)(deltas +
        ((size_t)((size_t)img * FH + row) * FW + col) * (NA * 4) + a * 4);
    float h = expf(d.z * 0.2f) * ah;
    float w = expf(d.w * 0.2f) * aw;
    float ccy = d.x * 0.1f * ah + acy;
    float ccx = d.y * 0.1f * aw + acx;
    float y1 = fminf(fmaxf(ccy - 0.5f * h, 0.f), 1.f);
    float x1 = fminf(fmaxf(ccx - 0.5f * w, 0.f), 1.f);
    float y2 = fminf(fmaxf(ccy + 0.5f * h, 0.f), 1.f);
    float x2 = fminf(fmaxf(ccx + 0.5f * w, 0.f), 1.f);
    g_boxes[img * PRE + p] = make_float4(y1, x1, y2, x2);
    g_area[img * PRE + p] = fmaxf(y2 - y1, 0.f) * fmaxf(x2 - x1, 0.f);
}

// ---------------- K5: register-resident greedy NMS, one block per image ----------------
// Thread tid owns candidates j = tid + 1024*s (s=0..5). Tile k (j in [32k,32k+32))
// is owned by warp (k%32), slot (k/32). Within-tile suppressor masks are
// precomputed in parallel; the serial path per tile is just the ballot loop.
#define SLOTS 6

__global__ void __launch_bounds__(1024, 1) k_nms(float* __restrict__ out) {
    __shared__ float4 accb[2][32];
    __shared__ float acca[2][32];
    __shared__ int s_nacc[2];
    __shared__ int s_emit, s_stop;

    int img = blockIdx.x, tid = threadIdx.x;
    int w = tid >> 5, lane = tid & 31;

    float4 bx[SLOTS];
    float ar[SLOTS];
    unsigned sup[SLOTS];
    unsigned liveMask = 0;

    #pragma unroll
    for (int s = 0; s < SLOTS; s++) {
        int j = tid + 1024 * s;
        if (j < PRE) {
            bx[s] = g_boxes[img * PRE + j];
            ar[s] = g_area[img * PRE + j];
            liveMask |= 1u << s;
        } else {
            bx[s] = make_float4(0.f, 0.f, 0.f, 0.f);
            ar[s] = 0.f;
        }
    }

    // precompute within-tile suppressor masks (pure geometry)
    #pragma unroll
    for (int s = 0; s < SLOTS; s++) {
        unsigned m = 0;
        float4 b = bx[s];
        float aj = ar[s];
        #pragma unroll 1
        for (int kk = 0; kk < 32; kk++) {
            float ky1 = __shfl_sync(0xFFFFFFFFu, b.x, kk);
            float kx1 = __shfl_sync(0xFFFFFFFFu, b.y, kk);
            float ky2 = __shfl_sync(0xFFFFFFFFu, b.z, kk);
            float kx2 = __shfl_sync(0xFFFFFFFFu, b.w, kk);
            float ak  = __shfl_sync(0xFFFFFFFFu, aj,  kk);
            float y1 = fmaxf(b.x, ky1), x1 = fmaxf(b.y, kx1);
            float y2 = fminf(b.z, ky2), x2 = fminf(b.w, kx2);
            float inter = fmaxf(y2 - y1, 0.f) * fmaxf(x2 - x1, 0.f);
            if (kk < lane && inter > IOU_THR * (ak + 1e-8f + aj - inter))
                m |= 1u << kk;
        }
        sup[s] = m;
    }

    if (tid == 0) { s_emit = 0; s_stop = 0; s_nacc[0] = 0; s_nacc[1] = 0; }
    __syncthreads();

    float4* out4 = (float4*)out + (size_t)img * POST;
    int p = 0;

    for (int k = 0; k < NTILES; k++) {
        int prev = p ^ 1;
        int nprev = s_nacc[prev];
        // ---- sweep own boxes vs previous tile's accepted ----
        if (nprev) {
            int jmin = k * 32;
            #pragma unroll
            for (int s = 0; s < SLOTS; s++) {
                int j = tid + 1024 * s;
                if (!((liveMask >> s) & 1) || j < jmin) continue;
                float4 c = bx[s];
                float acj = ar[s];
                for (int q = 0; q < nprev; q++) {
                    float4 b = accb[prev][q];
                    float y1 = fmaxf(b.x, c.x), x1 = fmaxf(b.y, c.y);
                    float y2 = fminf(b.z, c.z), x2 = fminf(b.w, c.w);
                    float inter = fmaxf(y2 - y1, 0.f) * fmaxf(x2 - x1, 0.f);
                    if (inter > IOU_THR * (acca[prev][q] + 1e-8f + acj - inter)) {
                        liveMask &= ~(1u << s);
                        break;
                    }
                }
            }
        }
        // ---- resolve tile k (owning warp only) ----
        if (w == (k & 31)) {
            int s = k >> 5;
            bool lv = (liveMask >> s) & 1;
            unsigned lm = __ballot_sync(0xFFFFFFFFu, lv);
            int emit0 = s_emit;
            int room = POST - emit0;
            unsigned acc = 0;
            int na = 0;
            unsigned rem = lm;
            unsigned mysup = sup[s];
            while (rem && na < room) {
                int j2 = __ffs(rem) - 1;
                acc |= 1u << j2;
                na++;
                unsigned dead = __ballot_sync(0xFFFFFFFFu, (mysup >> j2) & 1u);
                rem &= ~dead;
                rem &= ~(1u << j2);
            }
            if ((acc >> lane) & 1u) {
                int ord = __popc(acc & ((1u << lane) - 1u));
                accb[p][ord] = bx[s];
                acca[p][ord] = ar[s];
                out4[emit0 + ord] = bx[s];
            }
            if (lane == 0) {
                s_nacc[p] = na;
                s_emit = emit0 + na;
                if (emit0 + na >= POST) s_stop = 1;
            }
        }
        __syncthreads();
        if (s_stop) break;
        p ^= 1;
    }

    for (int r = s_emit + tid; r < POST; r += 1024)
        out4[r] = make_float4(0.f, 0.f, 0.f, 0.f);
}

// ---------------- launch ----------------
extern "C" void kernel_launch(void* const* d_in, const int* in_sizes, int n_in,
                              void* d_out, int out_size) {
    const float* deltas = (const float*)d_in[0];
    const float* labels = (const float*)d_in[1];
    const float* base   = (const float*)d_in[2];
    float* out = (float*)d_out;

    k_zero<<<(NB * NBIN2 + 255) / 256, 256>>>();                 // 1
    dim3 gh(HB, NB);
    k_histthresh<<<gh, 256>>>(labels);                           // 2
    dim3 gc(81, NB);
    k_compact<<<gc, 256>>>(labels);                              // 3
    k_segsort<<<(NB * NBIN2 + 7) / 8, 256>>>();                  // 4  <- ncu slot
    dim3 gdec((PRE + 255) / 256, NB);
    k_decode<<<gdec, 256>>>(deltas, base);                       // 5
    k_nms<<<NB, 1024>>>(out);                                    // 6
}

// round 8
// speedup vs baseline: 7.1685x; 2.3361x over previous
#include <cuda_runtime.h>
#include <cuda_bf16.h>
#include <math.h>

// Problem constants
#define NB 16
#define FH 192
#define FW 192
#define NA 9
#define N_ANCH (FH*FW*NA)   // 331776
#define PRE 6000
#define POST 1000
#define CAND_CAP 8192
#define IOU_THR 0.7f
#define NTILES ((PRE + 31) / 32)   // 188
#define NBIN2 2050                 // 0: <0.5 | 1..2048: [0.5,1) | 2049: >=1.0
#define SEG_MAX 512

// ---------------- static scratch (zero-initialized at module load;
// k_nms re-zeroes the counters at the end of every run) ----------------
__device__ unsigned g_hist2[NB * NBIN2];
__device__ unsigned g_bcnt[NB * NBIN2];
__device__ unsigned g_segstart[NB * NBIN2];
__device__ unsigned g_tbin2[NB];
__device__ unsigned g_ticket;
__device__ unsigned long long g_cand[NB * CAND_CAP];
__device__ float4 g_boxes[NB * PRE];
__device__ float  g_area[NB * PRE];

__device__ __forceinline__ int score_bin(unsigned k) {
    if (k >= 0x3F800000u) return NBIN2 - 1;
    if (k >= 0x3F000000u) return 1 + (int)((k >> 12) & 0x7FFu);
    return 0;
}

// ---------------- K1: histogram (bin0 via registers) + fused threshold ----------------
// grid (81, NB) x 256
__global__ void k_histthresh(const float* __restrict__ labels) {
    __shared__ unsigned sh[NBIN2];
    int img = blockIdx.y, tid = threadIdx.x;
    for (int t = tid; t < NBIN2; t += 256) sh[t] = 0;
    __syncthreads();
    const float4* L = (const float4*)(labels + (size_t)img * N_ANCH);
    int base = blockIdx.x * 1024;
    unsigned c0 = 0;
    #pragma unroll
    for (int p = 0; p < 4; p++) {
        float4 v = L[base + p * 256 + tid];
        int b0 = score_bin(__float_as_uint(v.x));
        int b1 = score_bin(__float_as_uint(v.y));
        int b2 = score_bin(__float_as_uint(v.z));
        int b3 = score_bin(__float_as_uint(v.w));
        if (b0) atomicAdd(&sh[b0], 1u); else c0++;
        if (b1) atomicAdd(&sh[b1], 1u); else c0++;
        if (b2) atomicAdd(&sh[b2], 1u); else c0++;
        if (b3) atomicAdd(&sh[b3], 1u); else c0++;
    }
    #pragma unroll
    for (int o = 16; o > 0; o >>= 1) c0 += __shfl_down_sync(0xFFFFFFFFu, c0, o);
    if ((tid & 31) == 0 && c0) atomicAdd(&sh[0], c0);
    __syncthreads();
    for (int t = tid; t < NBIN2; t += 256) {
        unsigned c = sh[t];
        if (c) atomicAdd(&g_hist2[img * NBIN2 + t], c);
    }
    // ---- last block: threshold + segment offsets for all images ----
    __threadfence();
    __shared__ int isLast;
    __syncthreads();
    if (tid == 0) isLast = (atomicAdd(&g_ticket, 1u) == (unsigned)(gridDim.x * gridDim.y - 1));
    __syncthreads();
    if (!isLast) return;

    int w = tid >> 5, lane = tid & 31;
    for (int im = w; im < NB; im += 8) {
        const unsigned* h = g_hist2 + im * NBIN2;
        unsigned* ss = g_segstart + im * NBIN2;
        unsigned run = 0;
        int T = -1;
        for (int c = 0; c < (NBIN2 + 31) / 32 && T < 0; c++) {
            int b = (NBIN2 - 1) - (c * 32 + lane);
            unsigned cnt = (b >= 0) ? h[b] : 0u;
            unsigned inc = cnt;
            #pragma unroll
            for (int o = 1; o < 32; o <<= 1) {
                unsigned v = __shfl_up_sync(0xFFFFFFFFu, inc, o);
                if (lane >= o) inc += v;
            }
            if (b >= 0) ss[b] = run + inc - cnt;
            unsigned tot = __shfl_sync(0xFFFFFFFFu, inc, 31);
            unsigned hit = __ballot_sync(0xFFFFFFFFu, b >= 0 && (run + inc) >= PRE);
            if (hit) T = (NBIN2 - 1) - (c * 32 + (__ffs(hit) - 1));
            run += tot;
        }
        if (lane == 0) g_tbin2[im] = (T < 0) ? 0u : (unsigned)T;
    }
}

// ---------------- K2: compact + exact bin placement ----------------
__global__ void k_compact(const float* __restrict__ labels) {
    int img = blockIdx.y, tid = threadIdx.x;
    const float4* L = (const float4*)(labels + (size_t)img * N_ANCH);
    int tb = (int)g_tbin2[img];
    const unsigned* ss = g_segstart + img * NBIN2;
    unsigned* bc = g_bcnt + img * NBIN2;
    int base = blockIdx.x * 1024;
    #pragma unroll
    for (int p = 0; p < 4; p++) {
        int f4 = base + p * 256 + tid;
        float4 v = L[f4];
        float e[4] = {v.x, v.y, v.z, v.w};
        #pragma unroll
        for (int c = 0; c < 4; c++) {
            unsigned k = __float_as_uint(e[c]);
            int b = score_bin(k);
            if (b >= tb) {
                unsigned pos = ss[b] + atomicAdd(&bc[b], 1u);
                if (pos < CAND_CAP)
                    g_cand[img * CAND_CAP + pos] =
                        ((unsigned long long)(~k) << 32) | (unsigned)(f4 * 4 + c);
            }
        }
    }
}

// ---------------- K3: per-bin segment sort + fused decode ----------------
__global__ void k_segsort_decode(const float* __restrict__ deltas,
                                 const float* __restrict__ basea) {
    __shared__ unsigned long long s[8][SEG_MAX];
    int gw = blockIdx.x * 8 + (threadIdx.x >> 5);
    int lane = threadIdx.x & 31;
    int img = gw / NBIN2;
    int b = gw % NBIN2;
    if (img >= NB) return;
    if (b < (int)g_tbin2[img]) return;
    int L = (int)g_bcnt[img * NBIN2 + b];
    if (L < 1) return;
    if (L > SEG_MAX) L = SEG_MAX;
    unsigned start = g_segstart[img * NBIN2 + b];
    if (start >= PRE) return;                       // fully beyond top-K
    const unsigned long long* seg = g_cand + img * CAND_CAP + start;
    unsigned long long (&sw)[SEG_MAX] = s[threadIdx.x >> 5];

    int P2 = 32; while (P2 < L) P2 <<= 1;
    for (int t = lane; t < P2; t += 32)
        sw[t] = (t < L && start + t < CAND_CAP) ? seg[t] : 0xFFFFFFFFFFFFFFFFull;
    __syncwarp();
    if (L > 1) {
        for (int k = 2; k <= P2; k <<= 1) {
            for (int j = k >> 1; j > 0; j >>= 1) {
                for (int i = lane; i < P2; i += 32) {
                    int ixj = i ^ j;
                    if (ixj > i) {
                        bool up = ((i & k) == 0);
                        unsigned long long a = sw[i], bb = sw[ixj];
                        if ((a > bb) == up) { sw[i] = bb; sw[ixj] = a; }
                    }
                }
                __syncwarp();
            }
        }
    }
    // ---- decode entries with pos < PRE ----
    for (int t = lane; t < L; t += 32) {
        unsigned pos = start + t;
        if (pos >= PRE || pos >= CAND_CAP) continue;
        unsigned idx = (unsigned)sw[t];
        int a = idx % NA;
        int cell = idx / NA;
        int row = cell / FW;
        int col = cell % FW;
        float cy = ((float)row + 0.5f) / (float)FH;
        float cx = ((float)col + 0.5f) / (float)FW;
        float b0 = basea[a * 4 + 0], b1 = basea[a * 4 + 1];
        float b2 = basea[a * 4 + 2], b3 = basea[a * 4 + 3];
        float ay1 = fminf(fmaxf(cy + b0, 0.f), 1.f);
        float ax1 = fminf(fmaxf(cx + b1, 0.f), 1.f);
        float ay2 = fminf(fmaxf(cy + b2, 0.f), 1.f);
        float ax2 = fminf(fmaxf(cx + b3, 0.f), 1.f);
        float ah = ay2 - ay1, aw = ax2 - ax1;
        float acy = ay1 + 0.5f * ah, acx = ax1 + 0.5f * aw;
        const float4 d = *(const float4*)(deltas +
            ((size_t)((size_t)img * FH + row) * FW + col) * (NA * 4) + a * 4);
        float h = expf(d.z * 0.2f) * ah;
        float w = expf(d.w * 0.2f) * aw;
        float ccy = d.x * 0.1f * ah + acy;
        float ccx = d.y * 0.1f * aw + acx;
        float y1 = fminf(fmaxf(ccy - 0.5f * h, 0.f), 1.f);
        float x1 = fminf(fmaxf(ccx - 0.5f * w, 0.f), 1.f);
        float y2 = fminf(fmaxf(ccy + 0.5f * h, 0.f), 1.f);
        float x2 = fminf(fmaxf(ccx + 0.5f * w, 0.f), 1.f);
        g_boxes[img * PRE + pos] = make_float4(y1, x1, y2, x2);
        g_area[img * PRE + pos] = fmaxf(y2 - y1, 0.f) * fmaxf(x2 - x1, 0.f);
    }
}

// ---------------- K4: lazy-sweep greedy NMS, one block per image ----------------
#define SM_SB   0
#define SM_SA   96000
#define SM_ACCB 120000
#define SM_ACCA 136000
#define SM_NMS_TOTAL 140000

__global__ void __launch_bounds__(1024, 1) k_nms(float* __restrict__ out) {
    extern __shared__ char sm[];
    float4* sb = (float4*)(sm + SM_SB);
    float* sa = (float*)(sm + SM_SA);
    float4* accb = (float4*)(sm + SM_ACCB);
    float* acca = (float*)(sm + SM_ACCA);
    __shared__ unsigned char s_livearr[32];
    __shared__ int s_nacc, s_stop;

    int img = blockIdx.x, tid = threadIdx.x;
    int w = tid >> 5, lane = tid & 31;

    for (int j = tid; j < PRE; j += 1024) {
        sb[j] = g_boxes[img * PRE + j];
        sa[j] = g_area[img * PRE + j];
    }
    if (tid == 0) { s_nacc = 0; s_stop = 0; }
    __syncthreads();

    float4* out4 = (float4*)out + (size_t)img * POST;

    for (int tile = 0; tile < NTILES; tile++) {
        int tbase = tile * 32;
        int n0 = s_nacc;
        // ---- Phase A: candidate tbase+w vs all accepted so far ----
        int c = tbase + w;
        bool kill = false;
        if (c < PRE) {
            float4 cb = sb[c];
            float ca = sa[c];
            for (int q = lane; q < n0; q += 32) {
                float4 b = accb[q];
                float y1 = fmaxf(b.x, cb.x), x1 = fmaxf(b.y, cb.y);
                float y2 = fminf(b.z, cb.z), x2 = fminf(b.w, cb.w);
                float inter = fmaxf(y2 - y1, 0.f) * fmaxf(x2 - x1, 0.f);
                kill |= (inter > IOU_THR * (acca[q] + 1e-8f + ca - inter));
            }
        }
        unsigned km = __ballot_sync(0xFFFFFFFFu, kill);
        if (lane == 0) s_livearr[w] = (c < PRE) && (km == 0);
        __syncthreads();
        // ---- Phase B: warp 0 resolves the tile ----
        if (w == 0) {
            int j = tbase + lane;
            bool lv = s_livearr[lane] != 0;
            float4 b = (j < PRE) ? sb[j] : make_float4(0.f, 0.f, 0.f, 0.f);
            float aj = (j < PRE) ? sa[j] : 0.f;
            unsigned m = 0;
            #pragma unroll 1
            for (int kk = 0; kk < 32; kk++) {
                float ky1 = __shfl_sync(0xFFFFFFFFu, b.x, kk);
                float kx1 = __shfl_sync(0xFFFFFFFFu, b.y, kk);
                float ky2 = __shfl_sync(0xFFFFFFFFu, b.z, kk);
                float kx2 = __shfl_sync(0xFFFFFFFFu, b.w, kk);
                float ak  = __shfl_sync(0xFFFFFFFFu, aj,  kk);
                float y1 = fmaxf(b.x, ky1), x1 = fmaxf(b.y, kx1);
                float y2 = fminf(b.z, ky2), x2 = fminf(b.w, kx2);
                float inter = fmaxf(y2 - y1, 0.f) * fmaxf(x2 - x1, 0.f);
                if (kk < lane && inter > IOU_THR * (ak + 1e-8f + aj - inter))
                    m |= 1u << kk;
            }
            unsigned rem = __ballot_sync(0xFFFFFFFFu, lv);
            int room = POST - n0;
            unsigned acc = 0;
            int na = 0;
            while (rem && na < room) {
                int j2 = __ffs(rem) - 1;
                acc |= 1u << j2;
                na++;
                unsigned dead = __ballot_sync(0xFFFFFFFFu, (m >> j2) & 1u);
                rem &= ~dead;
                rem &= ~(1u << j2);
            }
            if ((acc >> lane) & 1u) {
                int ord = __popc(acc & ((1u << lane) - 1u));
                accb[n0 + ord] = b;
                acca[n0 + ord] = aj;
                out4[n0 + ord] = b;
            }
            if (lane == 0) {
                s_nacc = n0 + na;
                if (n0 + na >= POST) s_stop = 1;
            }
        }
        __syncthreads();
        if (s_stop) break;
    }

    // zero-pad remaining rows
    for (int r = s_nacc + tid; r < POST; r += 1024)
        out4[r] = make_float4(0.f, 0.f, 0.f, 0.f);

    // ---- restore counters for the next run / graph replay ----
    unsigned* h = g_hist2 + img * NBIN2;
    unsigned* bc = g_bcnt + img * NBIN2;
    for (int t = tid; t < NBIN2; t += 1024) { h[t] = 0; bc[t] = 0; }
    if (img == 0 && tid == 0) g_ticket = 0;
}

// ---------------- launch (4 kernels; #4 = k_nms -> ncu slot) ----------------
extern "C" void kernel_launch(void* const* d_in, const int* in_sizes, int n_in,
                              void* d_out, int out_size) {
    const float* deltas = (const float*)d_in[0];
    const float* labels = (const float*)d_in[1];
    const float* base   = (const float*)d_in[2];
    float* out = (float*)d_out;

    cudaFuncSetAttribute(k_nms, cudaFuncAttributeMaxDynamicSharedMemorySize, SM_NMS_TOTAL);

    dim3 gq(81, NB);
    k_histthresh<<<gq, 256>>>(labels);                             // 1
    k_compact<<<gq, 256>>>(labels);                                // 2
    k_segsort_decode<<<(NB * NBIN2 + 7) / 8, 256>>>(deltas, base); // 3
    k_nms<<<NB, 1024, SM_NMS_TOTAL>>>(out);                        // 4  <- ncu slot
}

// round 9
// speedup vs baseline: 9.5812x; 1.3366x over previous
#include <cuda_runtime.h>
#include <cuda_bf16.h>
#include <math.h>

// Problem constants
#define NB 16
#define FH 192
#define FW 192
#define NA 9
#define N_ANCH (FH*FW*NA)   // 331776
#define PRE 6000
#define POST 1000
#define CAND_CAP 8192
#define IOU_THR 0.7f
#define NTILES ((PRE + 31) / 32)   // 188
#define NBIN2 2050                 // 0: <0.5 | 1..2048: [0.5,1) | 2049: >=1.0
#define SEG_MAX 512

// ---------------- static scratch (zero-initialized at module load;
// k_nms re-zeroes the counters at the end of every run) ----------------
__device__ unsigned g_hist2[NB * NBIN2];
__device__ unsigned g_bcnt[NB * NBIN2];
__device__ unsigned g_segstart[NB * NBIN2];
__device__ unsigned g_tbin2[NB];
__device__ unsigned g_ticket;
__device__ unsigned long long g_cand[NB * CAND_CAP];
__device__ float4 g_boxes[NB * PRE];
__device__ float  g_area[NB * PRE];

__device__ __forceinline__ int score_bin(unsigned k) {
    if (k >= 0x3F800000u) return NBIN2 - 1;
    if (k >= 0x3F000000u) return 1 + (int)((k >> 12) & 0x7FFu);
    return 0;
}

// ---------------- K1: histogram (bin0 via registers) + fused threshold ----------------
// grid (81, NB) x 256
__global__ void k_histthresh(const float* __restrict__ labels) {
    __shared__ unsigned sh[NBIN2];
    int img = blockIdx.y, tid = threadIdx.x;
    for (int t = tid; t < NBIN2; t += 256) sh[t] = 0;
    __syncthreads();
    const float4* L = (const float4*)(labels + (size_t)img * N_ANCH);
    int base = blockIdx.x * 1024;
    unsigned c0 = 0;
    #pragma unroll
    for (int p = 0; p < 4; p++) {
        float4 v = L[base + p * 256 + tid];
        int b0 = score_bin(__float_as_uint(v.x));
        int b1 = score_bin(__float_as_uint(v.y));
        int b2 = score_bin(__float_as_uint(v.z));
        int b3 = score_bin(__float_as_uint(v.w));
        if (b0) atomicAdd(&sh[b0], 1u); else c0++;
        if (b1) atomicAdd(&sh[b1], 1u); else c0++;
        if (b2) atomicAdd(&sh[b2], 1u); else c0++;
        if (b3) atomicAdd(&sh[b3], 1u); else c0++;
    }
    #pragma unroll
    for (int o = 16; o > 0; o >>= 1) c0 += __shfl_down_sync(0xFFFFFFFFu, c0, o);
    if ((tid & 31) == 0 && c0) atomicAdd(&sh[0], c0);
    __syncthreads();
    for (int t = tid; t < NBIN2; t += 256) {
        unsigned c = sh[t];
        if (c) atomicAdd(&g_hist2[img * NBIN2 + t], c);
    }
    // ---- last block: threshold + segment offsets for all images ----
    __threadfence();
    __shared__ int isLast;
    __syncthreads();
    if (tid == 0) isLast = (atomicAdd(&g_ticket, 1u) == (unsigned)(gridDim.x * gridDim.y - 1));
    __syncthreads();
    if (!isLast) return;

    int w = tid >> 5, lane = tid & 31;
    for (int im = w; im < NB; im += 8) {
        const unsigned* h = g_hist2 + im * NBIN2;
        unsigned* ss = g_segstart + im * NBIN2;
        unsigned run = 0;
        int T = -1;
        for (int c = 0; c < (NBIN2 + 31) / 32 && T < 0; c++) {
            int b = (NBIN2 - 1) - (c * 32 + lane);
            unsigned cnt = (b >= 0) ? h[b] : 0u;
            unsigned inc = cnt;
            #pragma unroll
            for (int o = 1; o < 32; o <<= 1) {
                unsigned v = __shfl_up_sync(0xFFFFFFFFu, inc, o);
                if (lane >= o) inc += v;
            }
            if (b >= 0) ss[b] = run + inc - cnt;
            unsigned tot = __shfl_sync(0xFFFFFFFFu, inc, 31);
            unsigned hit = __ballot_sync(0xFFFFFFFFu, b >= 0 && (run + inc) >= PRE);
            if (hit) T = (NBIN2 - 1) - (c * 32 + (__ffs(hit) - 1));
            run += tot;
        }
        if (lane == 0) g_tbin2[im] = (T < 0) ? 0u : (unsigned)T;
    }
}

// ---------------- K2: compact + exact bin placement ----------------
__global__ void k_compact(const float* __restrict__ labels) {
    int img = blockIdx.y, tid = threadIdx.x;
    const float4* L = (const float4*)(labels + (size_t)img * N_ANCH);
    int tb = (int)g_tbin2[img];
    const unsigned* ss = g_segstart + img * NBIN2;
    unsigned* bc = g_bcnt + img * NBIN2;
    int base = blockIdx.x * 1024;
    #pragma unroll
    for (int p = 0; p < 4; p++) {
        int f4 = base + p * 256 + tid;
        float4 v = L[f4];
        float e[4] = {v.x, v.y, v.z, v.w};
        #pragma unroll
        for (int c = 0; c < 4; c++) {
            unsigned k = __float_as_uint(e[c]);
            int b = score_bin(k);
            if (b >= tb) {
                unsigned pos = ss[b] + atomicAdd(&bc[b], 1u);
                if (pos < CAND_CAP)
                    g_cand[img * CAND_CAP + pos] =
                        ((unsigned long long)(~k) << 32) | (unsigned)(f4 * 4 + c);
            }
        }
    }
}

// ---------------- K3: per-bin segment sort + fused decode ----------------
__global__ void k_segsort_decode(const float* __restrict__ deltas,
                                 const float* __restrict__ basea) {
    __shared__ unsigned long long s[8][SEG_MAX];
    int gw = blockIdx.x * 8 + (threadIdx.x >> 5);
    int lane = threadIdx.x & 31;
    int img = gw / NBIN2;
    int b = gw % NBIN2;
    if (img >= NB) return;
    if (b < (int)g_tbin2[img]) return;
    int L = (int)g_bcnt[img * NBIN2 + b];
    if (L < 1) return;
    if (L > SEG_MAX) L = SEG_MAX;
    unsigned start = g_segstart[img * NBIN2 + b];
    if (start >= PRE) return;                       // fully beyond top-K
    const unsigned long long* seg = g_cand + img * CAND_CAP + start;
    unsigned long long (&sw)[SEG_MAX] = s[threadIdx.x >> 5];

    int P2 = 32; while (P2 < L) P2 <<= 1;
    for (int t = lane; t < P2; t += 32)
        sw[t] = (t < L && start + t < CAND_CAP) ? seg[t] : 0xFFFFFFFFFFFFFFFFull;
    __syncwarp();
    if (L > 1) {
        for (int k = 2; k <= P2; k <<= 1) {
            for (int j = k >> 1; j > 0; j >>= 1) {
                for (int i = lane; i < P2; i += 32) {
                    int ixj = i ^ j;
                    if (ixj > i) {
                        bool up = ((i & k) == 0);
                        unsigned long long a = sw[i], bb = sw[ixj];
                        if ((a > bb) == up) { sw[i] = bb; sw[ixj] = a; }
                    }
                }
                __syncwarp();
            }
        }
    }
    // ---- decode entries with pos < PRE ----
    for (int t = lane; t < L; t += 32) {
        unsigned pos = start + t;
        if (pos >= PRE || pos >= CAND_CAP) continue;
        unsigned idx = (unsigned)sw[t];
        int a = idx % NA;
        int cell = idx / NA;
        int row = cell / FW;
        int col = cell % FW;
        float cy = ((float)row + 0.5f) / (float)FH;
        float cx = ((float)col + 0.5f) / (float)FW;
        float b0 = basea[a * 4 + 0], b1 = basea[a * 4 + 1];
        float b2 = basea[a * 4 + 2], b3 = basea[a * 4 + 3];
        float ay1 = fminf(fmaxf(cy + b0, 0.f), 1.f);
        float ax1 = fminf(fmaxf(cx + b1, 0.f), 1.f);
        float ay2 = fminf(fmaxf(cy + b2, 0.f), 1.f);
        float ax2 = fminf(fmaxf(cx + b3, 0.f), 1.f);
        float ah = ay2 - ay1, aw = ax2 - ax1;
        float acy = ay1 + 0.5f * ah, acx = ax1 + 0.5f * aw;
        const float4 d = *(const float4*)(deltas +
            ((size_t)((size_t)img * FH + row) * FW + col) * (NA * 4) + a * 4);
        float h = expf(d.z * 0.2f) * ah;
        float w = expf(d.w * 0.2f) * aw;
        float ccy = d.x * 0.1f * ah + acy;
        float ccx = d.y * 0.1f * aw + acx;
        float y1 = fminf(fmaxf(ccy - 0.5f * h, 0.f), 1.f);
        float x1 = fminf(fmaxf(ccx - 0.5f * w, 0.f), 1.f);
        float y2 = fminf(fmaxf(ccy + 0.5f * h, 0.f), 1.f);
        float x2 = fminf(fmaxf(ccx + 0.5f * w, 0.f), 1.f);
        g_boxes[img * PRE + pos] = make_float4(y1, x1, y2, x2);
        g_area[img * PRE + pos] = fmaxf(y2 - y1, 0.f) * fmaxf(x2 - x1, 0.f);
    }
}

// ---------------- K4: lazy-sweep NMS with precomputed tile geometry ----------------
// Shared: boxes | areas | per-tile suppressor masks (precomputed in parallel)
//         | accepted boxes | accepted areas
#define SM_SB   0
#define SM_SA   96000
#define SM_SUP  120000           // NTILES*32*4 = 24064
#define SM_ACCB 144064           // 16-byte aligned
#define SM_ACCA 160064
#define SM_NMS_TOTAL 164096

__global__ void __launch_bounds__(1024, 1) k_nms(float* __restrict__ out) {
    extern __shared__ char sm[];
    float4* sb = (float4*)(sm + SM_SB);
    float* sa = (float*)(sm + SM_SA);
    unsigned* sup_sm = (unsigned*)(sm + SM_SUP);
    float4* accb = (float4*)(sm + SM_ACCB);
    float* acca = (float*)(sm + SM_ACCA);
    __shared__ unsigned char s_livearr[32];
    __shared__ int s_nacc, s_stop;

    int img = blockIdx.x, tid = threadIdx.x;
    int w = tid >> 5, lane = tid & 31;

    for (int j = tid; j < PRE; j += 1024) {
        sb[j] = g_boxes[img * PRE + j];
        sa[j] = g_area[img * PRE + j];
    }
    if (tid == 0) { s_nacc = 0; s_stop = 0; }
    __syncthreads();

    // ---- precompute within-tile suppressor masks (all tiles, in parallel) ----
    for (int t = w; t < NTILES; t += 32) {
        int j = t * 32 + lane;
        float4 b; float aj;
        if (j < PRE) { b = sb[j]; aj = sa[j]; }
        else { b = make_float4(0.f, 0.f, 0.f, 0.f); aj = 0.f; }
        unsigned m = 0;
        #pragma unroll 1
        for (int kk = 0; kk < 32; kk++) {
            float ky1 = __shfl_sync(0xFFFFFFFFu, b.x, kk);
            float kx1 = __shfl_sync(0xFFFFFFFFu, b.y, kk);
            float ky2 = __shfl_sync(0xFFFFFFFFu, b.z, kk);
            float kx2 = __shfl_sync(0xFFFFFFFFu, b.w, kk);
            float ak  = __shfl_sync(0xFFFFFFFFu, aj,  kk);
            float y1 = fmaxf(b.x, ky1), x1 = fmaxf(b.y, kx1);
            float y2 = fminf(b.z, ky2), x2 = fminf(b.w, kx2);
            float inter = fmaxf(y2 - y1, 0.f) * fmaxf(x2 - x1, 0.f);
            if (kk < lane && inter > IOU_THR * (ak + 1e-8f + aj - inter))
                m |= 1u << kk;
        }
        sup_sm[t * 32 + lane] = m;
    }
    __syncthreads();

    float4* out4 = (float4*)out + (size_t)img * POST;

    for (int tile = 0; tile < NTILES; tile++) {
        int tbase = tile * 32;
        int n0 = s_nacc;
        // ---- Phase A: candidate tbase+w vs all accepted so far ----
        int c = tbase + w;
        bool kill = false;
        if (c < PRE) {
            float4 cb = sb[c];
            float ca = sa[c];
            for (int q = lane; q < n0; q += 32) {
                float4 b = accb[q];
                float y1 = fmaxf(b.x, cb.x), x1 = fmaxf(b.y, cb.y);
                float y2 = fminf(b.z, cb.z), x2 = fminf(b.w, cb.w);
                float inter = fmaxf(y2 - y1, 0.f) * fmaxf(x2 - x1, 0.f);
                kill |= (inter > IOU_THR * (acca[q] + 1e-8f + ca - inter));
            }
        }
        unsigned km = __ballot_sync(0xFFFFFFFFu, kill);
        if (lane == 0) s_livearr[w] = (c < PRE) && (km == 0);
        __syncthreads();
        // ---- Phase B: warp 0 resolves the tile with the precomputed mask ----
        if (w == 0) {
            bool lv = s_livearr[lane] != 0;
            unsigned m = sup_sm[tbase + lane];
            unsigned rem = __ballot_sync(0xFFFFFFFFu, lv);
            int room = POST - n0;
            unsigned acc = 0;
            int na = 0;
            while (rem && na < room) {
                int j2 = __ffs(rem) - 1;
                acc |= 1u << j2;
                na++;
                unsigned dead = __ballot_sync(0xFFFFFFFFu, (m >> j2) & 1u);
                rem &= ~dead;
                rem &= ~(1u << j2);
            }
            if ((acc >> lane) & 1u) {
                int j = tbase + lane;
                int ord = __popc(acc & ((1u << lane) - 1u));
                float4 b = sb[j];
                accb[n0 + ord] = b;
                acca[n0 + ord] = sa[j];
                out4[n0 + ord] = b;
            }
            if (lane == 0) {
                s_nacc = n0 + na;
                if (n0 + na >= POST) s_stop = 1;
            }
        }
        __syncthreads();
        if (s_stop) break;
    }

    // zero-pad remaining rows
    for (int r = s_nacc + tid; r < POST; r += 1024)
        out4[r] = make_float4(0.f, 0.f, 0.f, 0.f);

    // ---- restore counters for the next run / graph replay ----
    unsigned* h = g_hist2 + img * NBIN2;
    unsigned* bc = g_bcnt + img * NBIN2;
    for (int t = tid; t < NBIN2; t += 1024) { h[t] = 0; bc[t] = 0; }
    if (img == 0 && tid == 0) g_ticket = 0;
}

// ---------------- launch (4 kernels; #4 = k_nms -> ncu slot) ----------------
extern "C" void kernel_launch(void* const* d_in, const int* in_sizes, int n_in,
                              void* d_out, int out_size) {
    const float* deltas = (const float*)d_in[0];
    const float* labels = (const float*)d_in[1];
    const float* base   = (const float*)d_in[2];
    float* out = (float*)d_out;

    cudaFuncSetAttribute(k_nms, cudaFuncAttributeMaxDynamicSharedMemorySize, SM_NMS_TOTAL);

    dim3 gq(81, NB);
    k_histthresh<<<gq, 256>>>(labels);                             // 1
    k_compact<<<gq, 256>>>(labels);                                // 2
    k_segsort_decode<<<(NB * NBIN2 + 7) / 8, 256>>>(deltas, base); // 3
    k_nms<<<NB, 1024, SM_NMS_TOTAL>>>(out);                        // 4  <- ncu slot
}